// round 1
// baseline (speedup 1.0000x reference)
#include <cuda_runtime.h>
#include <cuda_bf16.h>
#include <math.h>

// Problem constants
#define BB 1
#define CC 32
#define HH 128
#define WW 160
#define DD 48
#define HW (HH*WW)          // 20480

// Padded variance volume (zero halo for SAME conv): (C, D+2, H+2, W+2)
#define PD (DD+2)           // 50
#define PH (HH+2)           // 130
#define PW (WW+2)           // 162
#define ROWS   PW           // 162
#define SLICE  (PH*PW)      // 21060
#define CST    (PD*SLICE)   // 1,053,000 per channel

// Scratch (device globals are zero-initialized at module load; halo cells of
// g_var are never written, so SAME-padding zeros are free and persistent).
__device__ float g_rot[2][9];
__device__ float g_trans[2][3];
__device__ float g_featT[2][HW*CC];     // (view, y, x, c)  ~5.2 MB
__device__ float g_var[CC*CST];         // padded (c,d,h,w) ~134.8 MB
__device__ float g_cost[DD*HW];         // ~3.9 MB

// ---------------------------------------------------------------------------
// Stage 0: proj_v @ inv(proj_ref)  ->  rot (3x3), trans (3) for views 1,2
// proj matrices are affine: [[A, b],[0,0,0,1]]
// inv(ref) = [[A0^-1, -A0^-1 b0],[0,1]];  rot = Av A0^-1; trans = bv - rot b0
// ---------------------------------------------------------------------------
__global__ void prep_kernel(const float* __restrict__ proj)
{
    if (threadIdx.x != 0 || blockIdx.x != 0) return;
    float A0[9], b0[3];
    for (int r = 0; r < 3; ++r) {
        for (int c = 0; c < 3; ++c) A0[r*3+c] = proj[r*4+c];
        b0[r] = proj[r*4+3];
    }
    // adjugate inverse of A0
    float inv[9];
    inv[0] =  A0[4]*A0[8] - A0[5]*A0[7];
    inv[1] = -(A0[1]*A0[8] - A0[2]*A0[7]);
    inv[2] =  A0[1]*A0[5] - A0[2]*A0[4];
    inv[3] = -(A0[3]*A0[8] - A0[5]*A0[6]);
    inv[4] =  A0[0]*A0[8] - A0[2]*A0[6];
    inv[5] = -(A0[0]*A0[5] - A0[2]*A0[3]);
    inv[6] =  A0[3]*A0[7] - A0[4]*A0[6];
    inv[7] = -(A0[0]*A0[7] - A0[1]*A0[6]);
    inv[8] =  A0[0]*A0[4] - A0[1]*A0[3];
    float det = A0[0]*inv[0] + A0[1]*inv[3] + A0[2]*inv[6];
    float idet = 1.0f / det;
    for (int i = 0; i < 9; ++i) inv[i] *= idet;

    for (int v = 1; v < 3; ++v) {
        const float* P = proj + v*16;
        float Av[9], bv[3];
        for (int r = 0; r < 3; ++r) {
            for (int c = 0; c < 3; ++c) Av[r*3+c] = P[r*4+c];
            bv[r] = P[r*4+3];
        }
        float rot[9];
        for (int r = 0; r < 3; ++r)
            for (int c = 0; c < 3; ++c)
                rot[r*3+c] = Av[r*3+0]*inv[0*3+c] + Av[r*3+1]*inv[1*3+c] + Av[r*3+2]*inv[2*3+c];
        for (int r = 0; r < 3; ++r) {
            float t = bv[r] - (rot[r*3+0]*b0[0] + rot[r*3+1]*b0[1] + rot[r*3+2]*b0[2]);
            g_trans[v-1][r] = t;
        }
        for (int i = 0; i < 9; ++i) g_rot[v-1][i] = rot[i];
    }
}

// ---------------------------------------------------------------------------
// Stage 1: transpose feat1/feat2 from (C,H,W) to (H,W,C) so a bilinear corner
// reads 32 channels as 8 contiguous float4 (one 128B line per pixel).
// ---------------------------------------------------------------------------
__global__ void transpose_kernel(const float* __restrict__ f1,
                                 const float* __restrict__ f2)
{
    int idx = blockIdx.x * blockDim.x + threadIdx.x;     // over 2*C*HW
    if (idx >= 2*CC*HW) return;
    int v   = idx / (CC*HW);
    int r   = idx - v*CC*HW;
    int c   = r / HW;
    int pix = r - c*HW;
    const float* src = v ? f2 : f1;
    g_featT[v][pix*CC + c] = src[c*HW + pix];
}

// ---------------------------------------------------------------------------
// Stage 2: warp + variance.  One thread per (d,h,w): compute bilinear coords
// once per view, gather 32 channels per corner as float4, accumulate sum /
// sum-of-squares with the ref feature, emit variance into the padded volume.
// ---------------------------------------------------------------------------
__global__ void __launch_bounds__(256)
warp_var_kernel(const float* __restrict__ feat0,
                const float* __restrict__ depth_values)
{
    int idx = blockIdx.x * 256 + threadIdx.x;            // 983040 = 3840*256
    int w = idx % WW;
    int t = idx / WW;
    int h = t % HH;
    int d = t / HH;

    float depth = __ldg(depth_values + d);

    float4 s[8], q[8];
    const float* f0 = feat0 + h*WW + w;
#pragma unroll
    for (int cg = 0; cg < 8; ++cg) {
        float a = __ldg(f0 + (cg*4+0)*HW);
        float b = __ldg(f0 + (cg*4+1)*HW);
        float c = __ldg(f0 + (cg*4+2)*HW);
        float e = __ldg(f0 + (cg*4+3)*HW);
        s[cg] = make_float4(a, b, c, e);
        q[cg] = make_float4(a*a, b*b, c*c, e*e);
    }

    float fx = (float)w, fy = (float)h;

#pragma unroll
    for (int v = 0; v < 2; ++v) {
        float r0 = g_rot[v][0], r1 = g_rot[v][1], r2 = g_rot[v][2];
        float r3 = g_rot[v][3], r4 = g_rot[v][4], r5 = g_rot[v][5];
        float r6 = g_rot[v][6], r7 = g_rot[v][7], r8 = g_rot[v][8];
        float t0 = g_trans[v][0], t1 = g_trans[v][1], t2 = g_trans[v][2];

        float px = (r0*fx + r1*fy + r2) * depth + t0;
        float py = (r3*fx + r4*fy + r5) * depth + t1;
        float pz = (r6*fx + r7*fy + r8) * depth + t2;
        float gx = px / pz;
        float gy = py / pz;

        float x0f = floorf(gx), y0f = floorf(gy);
        float wx = gx - x0f, wy = gy - y0f;
        float x1f = x0f + 1.0f, y1f = y0f + 1.0f;

        float vx0 = (x0f >= 0.0f && x0f <= (float)(WW-1)) ? 1.0f : 0.0f;
        float vx1 = (x1f >= 0.0f && x1f <= (float)(WW-1)) ? 1.0f : 0.0f;
        float vy0 = (y0f >= 0.0f && y0f <= (float)(HH-1)) ? 1.0f : 0.0f;
        float vy1 = (y1f >= 0.0f && y1f <= (float)(HH-1)) ? 1.0f : 0.0f;

        float w00 = (1.0f-wx)*(1.0f-wy) * (vx0*vy0);
        float w10 = wx*(1.0f-wy)        * (vx1*vy0);
        float w01 = (1.0f-wx)*wy        * (vx0*vy1);
        float w11 = wx*wy               * (vx1*vy1);

        int x0 = (int)fminf(fmaxf(x0f, 0.0f), (float)(WW-1));
        int x1 = (int)fminf(fmaxf(x1f, 0.0f), (float)(WW-1));
        int y0 = (int)fminf(fmaxf(y0f, 0.0f), (float)(HH-1));
        int y1 = (int)fminf(fmaxf(y1f, 0.0f), (float)(HH-1));

        const float4* p00 = (const float4*)(&g_featT[v][(y0*WW + x0)*CC]);
        const float4* p10 = (const float4*)(&g_featT[v][(y0*WW + x1)*CC]);
        const float4* p01 = (const float4*)(&g_featT[v][(y1*WW + x0)*CC]);
        const float4* p11 = (const float4*)(&g_featT[v][(y1*WW + x1)*CC]);

#pragma unroll
        for (int cg = 0; cg < 8; ++cg) {
            float4 a = __ldg(p00 + cg);
            float4 b = __ldg(p10 + cg);
            float4 c = __ldg(p01 + cg);
            float4 e = __ldg(p11 + cg);
            float fx0 = w00*a.x + w10*b.x + w01*c.x + w11*e.x;
            float fy1_ = w00*a.y + w10*b.y + w01*c.y + w11*e.y;
            float fz = w00*a.z + w10*b.z + w01*c.z + w11*e.z;
            float fw = w00*a.w + w10*b.w + w01*c.w + w11*e.w;
            s[cg].x += fx0;  q[cg].x += fx0*fx0;
            s[cg].y += fy1_; q[cg].y += fy1_*fy1_;
            s[cg].z += fz;   q[cg].z += fz*fz;
            s[cg].w += fw;   q[cg].w += fw*fw;
        }
    }

    const float inv3 = 1.0f / 3.0f;
    int base = (d+1)*SLICE + (h+1)*ROWS + (w+1);
#pragma unroll
    for (int cg = 0; cg < 8; ++cg) {
        float m, var;
        m = s[cg].x * inv3; var = q[cg].x * inv3 - m*m;
        g_var[(cg*4+0)*CST + base] = var;
        m = s[cg].y * inv3; var = q[cg].y * inv3 - m*m;
        g_var[(cg*4+1)*CST + base] = var;
        m = s[cg].z * inv3; var = q[cg].z * inv3 - m*m;
        g_var[(cg*4+2)*CST + base] = var;
        m = s[cg].w * inv3; var = q[cg].w * inv3 - m*m;
        g_var[(cg*4+3)*CST + base] = var;
    }
}

// ---------------------------------------------------------------------------
// Stage 3: 3D conv (SAME, 3x3x3, C->1).  Thread = one w lane (warp covers 32
// consecutive w -> coalesced), register tile of 4 h x 2 d outputs.  Per
// channel: 27 weights in registers, 4x6 rows x 3 w-taps loads, 216 FMAs.
// Zero halo comes from the never-written padded cells of g_var.
// ---------------------------------------------------------------------------
__global__ void __launch_bounds__(128)
conv_kernel(const float* __restrict__ w_reg)
{
    int lane = threadIdx.x & 31;
    int tyy  = threadIdx.x >> 5;                   // 0..3
    int w  = blockIdx.x * 32 + lane;               // gridDim.x = 5
    int h0 = (blockIdx.y * 4 + tyy) * 4;           // gridDim.y = 8
    int d0 = blockIdx.z * 2;                       // gridDim.z = 24

    float acc[2][4];
#pragma unroll
    for (int od = 0; od < 2; ++od)
#pragma unroll
        for (int oh = 0; oh < 4; ++oh) acc[od][oh] = 0.0f;

    // padded coords: output (d0,h0,w) needs padded rows [d0..d0+3]x[h0..h0+5],
    // padded w columns [w..w+2]
    const float* basep0 = g_var + d0*SLICE + h0*ROWS + w;

    for (int c = 0; c < CC; ++c) {
        float wt[27];
#pragma unroll
        for (int i = 0; i < 27; ++i) wt[i] = __ldg(w_reg + c*27 + i);

        const float* basep = basep0 + c*CST;
#pragma unroll
        for (int rz = 0; rz < 4; ++rz) {
#pragma unroll
            for (int ry = 0; ry < 6; ++ry) {
                const float* rp = basep + rz*SLICE + ry*ROWS;
                float v0 = __ldg(rp + 0);
                float v1 = __ldg(rp + 1);
                float v2 = __ldg(rp + 2);
#pragma unroll
                for (int od = 0; od < 2; ++od) {
                    int dd = rz - od;
                    if (dd < 0 || dd > 2) continue;
#pragma unroll
                    for (int oh = 0; oh < 4; ++oh) {
                        int dy = ry - oh;
                        if (dy < 0 || dy > 2) continue;
                        const int wbase = dd*9 + dy*3;
                        acc[od][oh] = fmaf(wt[wbase+0], v0,
                                      fmaf(wt[wbase+1], v1,
                                      fmaf(wt[wbase+2], v2, acc[od][oh])));
                    }
                }
            }
        }
    }

#pragma unroll
    for (int od = 0; od < 2; ++od)
#pragma unroll
        for (int oh = 0; oh < 4; ++oh)
            g_cost[(d0+od)*HW + (h0+oh)*WW + w] = acc[od][oh];
}

// ---------------------------------------------------------------------------
// Stage 4: softmax over D, expected depth + max-prob confidence.
// b_reg shifts all logits equally -> cancels in softmax -> ignored.
// ---------------------------------------------------------------------------
__global__ void __launch_bounds__(128)
depth_kernel(const float* __restrict__ depth_values, float* __restrict__ out)
{
    int pix = blockIdx.x * 128 + threadIdx.x;      // 20480 = 160*128
    if (pix >= HW) return;

    float cv[DD];
    float m = -1e30f;
#pragma unroll
    for (int d = 0; d < DD; ++d) {
        cv[d] = g_cost[d*HW + pix];
        m = fmaxf(m, cv[d]);
    }
    float sum = 0.0f, dep = 0.0f, best = 0.0f;
#pragma unroll
    for (int d = 0; d < DD; ++d) {
        float e = expf(cv[d] - m);
        sum += e;
        dep += e * __ldg(depth_values + d);
        best = fmaxf(best, e);
    }
    float isum = 1.0f / sum;
    out[pix]      = dep * isum;     // depth
    out[HW + pix] = best * isum;    // photometric confidence
}

// ---------------------------------------------------------------------------
extern "C" void kernel_launch(void* const* d_in, const int* in_sizes, int n_in,
                              void* d_out, int out_size)
{
    const float* feat0 = (const float*)d_in[0];
    const float* feat1 = (const float*)d_in[1];
    const float* feat2 = (const float*)d_in[2];
    const float* proj  = (const float*)d_in[3];
    const float* dvals = (const float*)d_in[4];
    const float* wreg  = (const float*)d_in[5];
    // d_in[6] = b_reg (cancels in softmax), d_in[7] = num_depth (compile-time)
    float* out = (float*)d_out;

    prep_kernel<<<1, 1>>>(proj);
    transpose_kernel<<<(2*CC*HW + 255)/256, 256>>>(feat1, feat2);
    warp_var_kernel<<<(DD*HH*WW)/256, 256>>>(feat0, dvals);
    conv_kernel<<<dim3(WW/32, HH/16, DD/2), 128>>>(wreg);
    depth_kernel<<<(HW + 127)/128, 128>>>(dvals, out);
}

// round 2
// speedup vs baseline: 1.1453x; 1.1453x over previous
#include <cuda_runtime.h>
#include <cuda_bf16.h>
#include <math.h>

// Problem constants
#define BB 1
#define CC 32
#define HH 128
#define WW 160
#define DD 48
#define HW (HH*WW)          // 20480

// Padded variance volume (zero halo for SAME conv): (C, D+2, H+2, W+4pad)
// ROWS=164 keeps every conv row load 16B-aligned (tile w starts % 4 == 0).
#define PD (DD+2)           // 50
#define PH (HH+2)           // 130
#define ROWS   164
#define SLICE  (PH*ROWS)    // 21320
#define CST    (PD*SLICE)   // 1,066,000 per channel

// Scratch (device globals are zero-initialized at module load; halo cells of
// g_var are never written, so SAME-padding zeros are free and persistent).
__device__ float g_rot[2][9];
__device__ float g_trans[2][3];
__device__ float g_featT[3][HW*CC];     // (view, y, x, c)  channel-last
__device__ float g_var[CC*CST];         // padded (c,d,h,w) ~136 MB
__device__ float g_cost[DD*HW];         // ~3.9 MB

// ---------------------------------------------------------------------------
// Stage 0: proj_v @ inv(proj_ref) -> rot(3x3), trans(3) for views 1,2
// ---------------------------------------------------------------------------
__global__ void prep_kernel(const float* __restrict__ proj)
{
    if (threadIdx.x != 0 || blockIdx.x != 0) return;
    float A0[9], b0[3];
    for (int r = 0; r < 3; ++r) {
        for (int c = 0; c < 3; ++c) A0[r*3+c] = proj[r*4+c];
        b0[r] = proj[r*4+3];
    }
    float inv[9];
    inv[0] =  A0[4]*A0[8] - A0[5]*A0[7];
    inv[1] = -(A0[1]*A0[8] - A0[2]*A0[7]);
    inv[2] =  A0[1]*A0[5] - A0[2]*A0[4];
    inv[3] = -(A0[3]*A0[8] - A0[5]*A0[6]);
    inv[4] =  A0[0]*A0[8] - A0[2]*A0[6];
    inv[5] = -(A0[0]*A0[5] - A0[2]*A0[3]);
    inv[6] =  A0[3]*A0[7] - A0[4]*A0[6];
    inv[7] = -(A0[0]*A0[7] - A0[1]*A0[6]);
    inv[8] =  A0[0]*A0[4] - A0[1]*A0[3];
    float det = A0[0]*inv[0] + A0[1]*inv[3] + A0[2]*inv[6];
    float idet = 1.0f / det;
    for (int i = 0; i < 9; ++i) inv[i] *= idet;

    for (int v = 1; v < 3; ++v) {
        const float* P = proj + v*16;
        float Av[9], bv[3];
        for (int r = 0; r < 3; ++r) {
            for (int c = 0; c < 3; ++c) Av[r*3+c] = P[r*4+c];
            bv[r] = P[r*4+3];
        }
        float rot[9];
        for (int r = 0; r < 3; ++r)
            for (int c = 0; c < 3; ++c)
                rot[r*3+c] = Av[r*3+0]*inv[0*3+c] + Av[r*3+1]*inv[1*3+c] + Av[r*3+2]*inv[2*3+c];
        for (int r = 0; r < 3; ++r)
            g_trans[v-1][r] = bv[r] - (rot[r*3+0]*b0[0] + rot[r*3+1]*b0[1] + rot[r*3+2]*b0[2]);
        for (int i = 0; i < 9; ++i) g_rot[v-1][i] = rot[i];
    }
}

// ---------------------------------------------------------------------------
// Stage 1: tiled transpose (C,H,W) -> (H,W,C) for all 3 views.
// blockDim (32,8); grid (HW/32, 3)
// ---------------------------------------------------------------------------
__global__ void transpose_kernel(const float* __restrict__ f0,
                                 const float* __restrict__ f1,
                                 const float* __restrict__ f2)
{
    __shared__ float t[32][33];
    int v  = blockIdx.y;
    int p0 = blockIdx.x * 32;
    int tx = threadIdx.x, ty = threadIdx.y;
    const float* src = (v == 0) ? f0 : (v == 1) ? f1 : f2;

#pragma unroll
    for (int j = ty; j < 32; j += 8)
        t[j][tx] = src[j*HW + p0 + tx];      // j = channel, tx = pixel
    __syncthreads();
#pragma unroll
    for (int j = ty; j < 32; j += 8)
        g_featT[v][(p0 + j)*CC + tx] = t[tx][j];  // coalesced over channel
}

// ---------------------------------------------------------------------------
// Stage 2: warp+variance, channel-lane layout.
// One block per (d,h): 256 threads = 8 warps.  Phase A: 320 threads compute
// bilinear weights + 4 gather addresses per (view,w) into smem.  Phase B:
// each warp owns 20 voxels, lane = channel -> all gathers are single-
// wavefront coalesced 128B loads.  Phase C: conflict-free smem stage, then
// w-coalesced stores into the padded variance volume.
// ---------------------------------------------------------------------------
__global__ void __launch_bounds__(256)
warp_var_kernel(const float* __restrict__ depth_values)
{
    __shared__ float4 s_wgt[2][WW];
    __shared__ int4   s_adr[2][WW];
    __shared__ float  s_var[CC*161];

    int blk = blockIdx.x;                  // 0 .. DD*HH-1
    int d = blk / HH;
    int h = blk - d*HH;
    int tid = threadIdx.x;

    float depth = __ldg(depth_values + d);

    // Phase A: coords for 2 views x 160 w (only first 320 lanes... 256 thr ->
    // loop twice)
    for (int t = tid; t < 2*WW; t += 256) {
        int v = t / WW;
        int w = t - v*WW;
        float fx = (float)w, fy = (float)h;

        float px = (g_rot[v][0]*fx + g_rot[v][1]*fy + g_rot[v][2]) * depth + g_trans[v][0];
        float py = (g_rot[v][3]*fx + g_rot[v][4]*fy + g_rot[v][5]) * depth + g_trans[v][1];
        float pz = (g_rot[v][6]*fx + g_rot[v][7]*fy + g_rot[v][8]) * depth + g_trans[v][2];
        float gx = px / pz;
        float gy = py / pz;

        float x0f = floorf(gx), y0f = floorf(gy);
        float wx = gx - x0f, wy = gy - y0f;
        float x1f = x0f + 1.0f, y1f = y0f + 1.0f;

        float vx0 = (x0f >= 0.0f && x0f <= (float)(WW-1)) ? 1.0f : 0.0f;
        float vx1 = (x1f >= 0.0f && x1f <= (float)(WW-1)) ? 1.0f : 0.0f;
        float vy0 = (y0f >= 0.0f && y0f <= (float)(HH-1)) ? 1.0f : 0.0f;
        float vy1 = (y1f >= 0.0f && y1f <= (float)(HH-1)) ? 1.0f : 0.0f;

        float w00 = (1.0f-wx)*(1.0f-wy) * (vx0*vy0);
        float w10 = wx*(1.0f-wy)        * (vx1*vy0);
        float w01 = (1.0f-wx)*wy        * (vx0*vy1);
        float w11 = wx*wy               * (vx1*vy1);

        int x0 = (int)fminf(fmaxf(x0f, 0.0f), (float)(WW-1));
        int x1 = (int)fminf(fmaxf(x1f, 0.0f), (float)(WW-1));
        int y0 = (int)fminf(fmaxf(y0f, 0.0f), (float)(HH-1));
        int y1 = (int)fminf(fmaxf(y1f, 0.0f), (float)(HH-1));

        int a00 = (y0*WW + x0)*CC;
        int a10 = (y0*WW + x1)*CC;
        int a01 = (y1*WW + x0)*CC;
        int a11 = (y1*WW + x1)*CC;

        s_wgt[v][w] = make_float4(w00, w10, w01, w11);
        s_adr[v][w] = make_int4(a00, a10, a01, a11);
    }
    __syncthreads();

    // Phase B: warp = 20 voxels, lane = channel
    int lane = tid & 31;
    int warp = tid >> 5;
    const float* f0 = g_featT[0] + (h*WW)*CC + lane;
    const float* f1 = g_featT[1] + lane;
    const float* f2 = g_featT[2] + lane;

#pragma unroll 4
    for (int i = 0; i < 20; ++i) {
        int w = warp*20 + i;
        float ref = __ldg(f0 + w*CC);
        float s = ref, q = ref*ref;

        {
            float4 wt = s_wgt[0][w];
            int4   ad = s_adr[0][w];
            float f = wt.x*__ldg(f1 + ad.x) + wt.y*__ldg(f1 + ad.y)
                    + wt.z*__ldg(f1 + ad.z) + wt.w*__ldg(f1 + ad.w);
            s += f; q += f*f;
        }
        {
            float4 wt = s_wgt[1][w];
            int4   ad = s_adr[1][w];
            float f = wt.x*__ldg(f2 + ad.x) + wt.y*__ldg(f2 + ad.y)
                    + wt.z*__ldg(f2 + ad.z) + wt.w*__ldg(f2 + ad.w);
            s += f; q += f*f;
        }

        const float inv3 = (1.0f/3.0f);
        float m = s * inv3;
        s_var[lane*161 + w] = q * inv3 - m*m;
    }
    __syncthreads();

    // Phase C: coalesced writeout into padded volume
    int base = (d+1)*SLICE + (h+1)*ROWS + 1;
    for (int i = tid; i < CC*WW; i += 256) {
        int c = i / WW;
        int w = i - c*WW;
        g_var[c*CST + base + w] = s_var[c*161 + w];
    }
}

// ---------------------------------------------------------------------------
// Stage 3: 3D conv (SAME, 3x3x3, C->1), smem-tiled.
// Block 256 threads, tile (d=4, h=16, w=32); per channel the padded
// 6x18x36 tile is bulk-loaded as float4, then each thread computes a
// (2d x 1h x 4w) register tile from smem.
// ---------------------------------------------------------------------------
__global__ void __launch_bounds__(256)
conv_kernel(const float* __restrict__ w_reg)
{
    __shared__ float tile[6*18*36];     // 15552 B
    __shared__ float ws[CC*27];

    int tid = threadIdx.x;
    int wq = tid & 7;                   // 0..7  -> w quad
    int hg = (tid >> 3) & 15;           // 0..15 -> h
    int dg = tid >> 7;                  // 0..1  -> d pair

    int W0 = blockIdx.x * 32;           // padded w window [W0, W0+35]
    int H0 = blockIdx.y * 16;           // padded h rows  [H0, H0+17]
    int D0 = blockIdx.z * 4;            // padded d rows  [D0, D0+5]

    for (int i = tid; i < CC*27; i += 256) ws[i] = w_reg[i];

    const float* gbase = g_var + (size_t)D0*SLICE + H0*ROWS + W0;

    float acc[2][4];
#pragma unroll
    for (int od = 0; od < 2; ++od)
#pragma unroll
        for (int wi = 0; wi < 4; ++wi) acc[od][wi] = 0.0f;

    for (int c = 0; c < CC; ++c) {
        __syncthreads();
        const float* gc = gbase + (size_t)c*CST;
        for (int i = tid; i < 108*9; i += 256) {
            int row = i / 9;            // 0..107  (rz*18 + ry)
            int v4  = i - row*9;
            int rz  = row / 18;
            int ry  = row - rz*18;
            float4 val = *(const float4*)(gc + rz*SLICE + ry*ROWS + v4*4);
            *(float4*)(tile + row*36 + v4*4) = val;
        }
        __syncthreads();

        float wt[27];
#pragma unroll
        for (int i = 0; i < 27; ++i) wt[i] = ws[c*27 + i];

#pragma unroll
        for (int rz = 0; rz < 4; ++rz) {
            int zrow = dg*2 + rz;
#pragma unroll
            for (int dy = 0; dy < 3; ++dy) {
                const float* rp = tile + (zrow*18 + hg + dy)*36 + wq*4;
                float4 A  = *(const float4*)rp;
                float4 Bv = *(const float4*)(rp + 4);
                float v0=A.x, v1=A.y, v2=A.z, v3=A.w, v4=Bv.x, v5=Bv.y;
                float vv[6] = {v0,v1,v2,v3,v4,v5};
#pragma unroll
                for (int od = 0; od < 2; ++od) {
                    int dz = rz - od;
                    if (dz < 0 || dz > 2) continue;
#pragma unroll
                    for (int kx = 0; kx < 3; ++kx) {
                        float wv = wt[dz*9 + dy*3 + kx];
#pragma unroll
                        for (int wi = 0; wi < 4; ++wi)
                            acc[od][wi] = fmaf(wv, vv[wi+kx], acc[od][wi]);
                    }
                }
            }
        }
    }

#pragma unroll
    for (int od = 0; od < 2; ++od)
#pragma unroll
        for (int wi = 0; wi < 4; ++wi)
            g_cost[(D0 + dg*2 + od)*HW + (H0 + hg)*WW + W0 + wq*4 + wi] = acc[od][wi];
}

// ---------------------------------------------------------------------------
// Stage 4: softmax over D, expected depth + max-prob confidence.
// b_reg shifts all logits equally -> cancels in softmax -> ignored.
// ---------------------------------------------------------------------------
__global__ void __launch_bounds__(128)
depth_kernel(const float* __restrict__ depth_values, float* __restrict__ out)
{
    int pix = blockIdx.x * 128 + threadIdx.x;
    if (pix >= HW) return;

    float cv[DD];
    float m = -1e30f;
#pragma unroll
    for (int d = 0; d < DD; ++d) {
        cv[d] = g_cost[d*HW + pix];
        m = fmaxf(m, cv[d]);
    }
    float sum = 0.0f, dep = 0.0f, best = 0.0f;
#pragma unroll
    for (int d = 0; d < DD; ++d) {
        float e = expf(cv[d] - m);
        sum += e;
        dep += e * __ldg(depth_values + d);
        best = fmaxf(best, e);
    }
    float isum = 1.0f / sum;
    out[pix]      = dep * isum;
    out[HW + pix] = best * isum;
}

// ---------------------------------------------------------------------------
extern "C" void kernel_launch(void* const* d_in, const int* in_sizes, int n_in,
                              void* d_out, int out_size)
{
    const float* feat0 = (const float*)d_in[0];
    const float* feat1 = (const float*)d_in[1];
    const float* feat2 = (const float*)d_in[2];
    const float* proj  = (const float*)d_in[3];
    const float* dvals = (const float*)d_in[4];
    const float* wreg  = (const float*)d_in[5];
    float* out = (float*)d_out;

    prep_kernel<<<1, 1>>>(proj);
    transpose_kernel<<<dim3(HW/32, 3), dim3(32, 8)>>>(feat0, feat1, feat2);
    warp_var_kernel<<<DD*HH, 256>>>(dvals);
    conv_kernel<<<dim3(WW/32, HH/16, DD/4), 256>>>(wreg);
    depth_kernel<<<(HW + 127)/128, 128>>>(dvals, out);
}

// round 3
// speedup vs baseline: 1.4016x; 1.2238x over previous
#include <cuda_runtime.h>
#include <cuda_bf16.h>
#include <math.h>

// Problem constants
#define BB 1
#define CC 32
#define HH 128
#define WW 160
#define DD 48
#define HW (HH*WW)          // 20480

// Padded per-k partial volumes S_k: (27, D+2, H+2, W+pad)
#define PD (DD+2)           // 50
#define PH (HH+2)           // 130
#define ROWS   164
#define SLICE  (PH*ROWS)    // 21320
#define CSTS   (PD*SLICE)   // 1,066,000 per k-volume

// Device globals are zero-initialized at module load; halo cells of g_S are
// never written, so SAME-padding zeros are free and persistent.
__device__ float g_rot[2][9];
__device__ float g_trans[2][3];
__device__ float g_featT[3][HW*CC];          // (view, y, x, c) channel-last
__device__ float g_S[27u*CSTS];              // 27 padded partial volumes ~115MB
__device__ float g_cost[DD*HW];              // ~3.9 MB

#define FFMA2(d, a, b, c) \
    asm("fma.rn.f32x2 %0, %1, %2, %3;" : "=l"(d) : "l"(a), "l"(b), "l"(c))
#define PACK2(out, lo, hi) \
    asm("mov.b64 %0, {%1, %2};" : "=l"(out) : "f"(lo), "f"(hi))
#define UNPACK2(lo, hi, in) \
    asm("mov.b64 {%0, %1}, %2;" : "=f"(lo), "=f"(hi) : "l"(in))

// ---------------------------------------------------------------------------
// Stage 0: proj_v @ inv(proj_ref) -> rot(3x3), trans(3) for views 1,2
// ---------------------------------------------------------------------------
__global__ void prep_kernel(const float* __restrict__ proj)
{
    if (threadIdx.x != 0 || blockIdx.x != 0) return;
    float A0[9], b0[3];
    for (int r = 0; r < 3; ++r) {
        for (int c = 0; c < 3; ++c) A0[r*3+c] = proj[r*4+c];
        b0[r] = proj[r*4+3];
    }
    float inv[9];
    inv[0] =  A0[4]*A0[8] - A0[5]*A0[7];
    inv[1] = -(A0[1]*A0[8] - A0[2]*A0[7]);
    inv[2] =  A0[1]*A0[5] - A0[2]*A0[4];
    inv[3] = -(A0[3]*A0[8] - A0[5]*A0[6]);
    inv[4] =  A0[0]*A0[8] - A0[2]*A0[6];
    inv[5] = -(A0[0]*A0[5] - A0[2]*A0[3]);
    inv[6] =  A0[3]*A0[7] - A0[4]*A0[6];
    inv[7] = -(A0[0]*A0[7] - A0[1]*A0[6]);
    inv[8] =  A0[0]*A0[4] - A0[1]*A0[3];
    float det = A0[0]*inv[0] + A0[1]*inv[3] + A0[2]*inv[6];
    float idet = 1.0f / det;
    for (int i = 0; i < 9; ++i) inv[i] *= idet;

    for (int v = 1; v < 3; ++v) {
        const float* P = proj + v*16;
        float Av[9], bv[3];
        for (int r = 0; r < 3; ++r) {
            for (int c = 0; c < 3; ++c) Av[r*3+c] = P[r*4+c];
            bv[r] = P[r*4+3];
        }
        float rot[9];
        for (int r = 0; r < 3; ++r)
            for (int c = 0; c < 3; ++c)
                rot[r*3+c] = Av[r*3+0]*inv[0*3+c] + Av[r*3+1]*inv[1*3+c] + Av[r*3+2]*inv[2*3+c];
        for (int r = 0; r < 3; ++r)
            g_trans[v-1][r] = bv[r] - (rot[r*3+0]*b0[0] + rot[r*3+1]*b0[1] + rot[r*3+2]*b0[2]);
        for (int i = 0; i < 9; ++i) g_rot[v-1][i] = rot[i];
    }
}

// ---------------------------------------------------------------------------
// Stage 1: tiled transpose (C,H,W) -> (H,W,C) for all 3 views.
// ---------------------------------------------------------------------------
__global__ void transpose_kernel(const float* __restrict__ f0,
                                 const float* __restrict__ f1,
                                 const float* __restrict__ f2)
{
    __shared__ float t[32][33];
    int v  = blockIdx.y;
    int p0 = blockIdx.x * 32;
    int tx = threadIdx.x, ty = threadIdx.y;
    const float* src = (v == 0) ? f0 : (v == 1) ? f1 : f2;

#pragma unroll
    for (int j = ty; j < 32; j += 8)
        t[j][tx] = src[j*HW + p0 + tx];
    __syncthreads();
#pragma unroll
    for (int j = ty; j < 32; j += 8)
        g_featT[v][(p0 + j)*CC + tx] = t[tx][j];
}

// ---------------------------------------------------------------------------
// Stage 2: warp + variance + fused channel-reduction GEMM.
// Block per (d,h), 256 threads.
//  A: bilinear weights + gather addresses for 2 views x 160 w (+ packed
//     weight prep into smem).
//  B: warp = 20 voxels, lane = channel -> coalesced 128B gathers; variance
//     staged to smem s_var[c][w].
//  D: thread = w (160 active): cache 32 channel variances as 16 f32x2 regs,
//     then 27 dot products via FFMA2 against smem-broadcast packed weights;
//     write S_k into 27 padded volumes (w-coalesced).
// ---------------------------------------------------------------------------
__global__ void __launch_bounds__(256)
warp_var_kernel(const float* __restrict__ depth_values,
                const float* __restrict__ w_reg)
{
    __shared__ float4 s_wgt[2][WW];
    __shared__ int4   s_adr[2][WW];
    __shared__ float  s_var[CC*161];
    __shared__ unsigned long long s_pwt[27*16];   // packed (c,c+1) weights

    int blk = blockIdx.x;                  // 0 .. DD*HH-1
    int d = blk / HH;
    int h = blk - d*HH;
    int tid = threadIdx.x;

    float depth = __ldg(depth_values + d);

    // Phase A: projection coords per (view, w)
    for (int t = tid; t < 2*WW; t += 256) {
        int v = t / WW;
        int w = t - v*WW;
        float fx = (float)w, fy = (float)h;

        float px = (g_rot[v][0]*fx + g_rot[v][1]*fy + g_rot[v][2]) * depth + g_trans[v][0];
        float py = (g_rot[v][3]*fx + g_rot[v][4]*fy + g_rot[v][5]) * depth + g_trans[v][1];
        float pz = (g_rot[v][6]*fx + g_rot[v][7]*fy + g_rot[v][8]) * depth + g_trans[v][2];
        float gx = px / pz;
        float gy = py / pz;

        float x0f = floorf(gx), y0f = floorf(gy);
        float wx = gx - x0f, wy = gy - y0f;
        float x1f = x0f + 1.0f, y1f = y0f + 1.0f;

        float vx0 = (x0f >= 0.0f && x0f <= (float)(WW-1)) ? 1.0f : 0.0f;
        float vx1 = (x1f >= 0.0f && x1f <= (float)(WW-1)) ? 1.0f : 0.0f;
        float vy0 = (y0f >= 0.0f && y0f <= (float)(HH-1)) ? 1.0f : 0.0f;
        float vy1 = (y1f >= 0.0f && y1f <= (float)(HH-1)) ? 1.0f : 0.0f;

        float w00 = (1.0f-wx)*(1.0f-wy) * (vx0*vy0);
        float w10 = wx*(1.0f-wy)        * (vx1*vy0);
        float w01 = (1.0f-wx)*wy        * (vx0*vy1);
        float w11 = wx*wy               * (vx1*vy1);

        int x0 = (int)fminf(fmaxf(x0f, 0.0f), (float)(WW-1));
        int x1 = (int)fminf(fmaxf(x1f, 0.0f), (float)(WW-1));
        int y0 = (int)fminf(fmaxf(y0f, 0.0f), (float)(HH-1));
        int y1 = (int)fminf(fmaxf(y1f, 0.0f), (float)(HH-1));

        s_wgt[v][w] = make_float4(w00, w10, w01, w11);
        s_adr[v][w] = make_int4((y0*WW + x0)*CC, (y0*WW + x1)*CC,
                                (y1*WW + x0)*CC, (y1*WW + x1)*CC);
    }

    // Packed weights: s_pwt[k][c2] = (wt[2c2][k], wt[2c2+1][k])
    for (int i = tid; i < 27*16; i += 256) {
        int k  = i / 16;
        int c2 = i - k*16;
        float lo = __ldg(w_reg + (2*c2    )*27 + k);
        float hi = __ldg(w_reg + (2*c2 + 1)*27 + k);
        unsigned long long p; PACK2(p, lo, hi);
        s_pwt[i] = p;
    }
    __syncthreads();

    // Phase B: warp = 20 voxels, lane = channel
    int lane = tid & 31;
    int warp = tid >> 5;
    const float* f0 = g_featT[0] + (h*WW)*CC + lane;
    const float* f1 = g_featT[1] + lane;
    const float* f2 = g_featT[2] + lane;

#pragma unroll 4
    for (int i = 0; i < 20; ++i) {
        int w = warp*20 + i;
        float ref = __ldg(f0 + w*CC);
        float s = ref, q = ref*ref;

        {
            float4 wt = s_wgt[0][w];
            int4   ad = s_adr[0][w];
            float f = wt.x*__ldg(f1 + ad.x) + wt.y*__ldg(f1 + ad.y)
                    + wt.z*__ldg(f1 + ad.z) + wt.w*__ldg(f1 + ad.w);
            s += f; q += f*f;
        }
        {
            float4 wt = s_wgt[1][w];
            int4   ad = s_adr[1][w];
            float f = wt.x*__ldg(f2 + ad.x) + wt.y*__ldg(f2 + ad.y)
                    + wt.z*__ldg(f2 + ad.z) + wt.w*__ldg(f2 + ad.w);
            s += f; q += f*f;
        }

        const float inv3 = (1.0f/3.0f);
        float m = s * inv3;
        s_var[lane*161 + w] = q * inv3 - m*m;
    }
    __syncthreads();

    // Phase D: per-w channel-reduction dot products (27 k-taps)
    if (tid < WW) {
        int w = tid;
        unsigned long long var2[16];
#pragma unroll
        for (int c2 = 0; c2 < 16; ++c2) {
            float lo = s_var[(2*c2    )*161 + w];
            float hi = s_var[(2*c2 + 1)*161 + w];
            PACK2(var2[c2], lo, hi);
        }

        float* outp = g_S + (size_t)(d+1)*SLICE + (h+1)*ROWS + (w+1);
#pragma unroll
        for (int k = 0; k < 27; ++k) {
            const unsigned long long* pw = s_pwt + k*16;
            unsigned long long accA = 0ull, accB = 0ull;
#pragma unroll
            for (int c2 = 0; c2 < 16; c2 += 2) {
                FFMA2(accA, var2[c2],   pw[c2],   accA);
                FFMA2(accB, var2[c2+1], pw[c2+1], accB);
            }
            float a0, a1, b0v, b1v;
            UNPACK2(a0, a1, accA);
            UNPACK2(b0v, b1v, accB);
            outp[(size_t)k*CSTS] = (a0 + a1) + (b0v + b1v);
        }
    }
}

// ---------------------------------------------------------------------------
// Stage 3: shifted-sum of the 27 partial volumes -> cost.
// cost(d,h,w) = sum_k S_k[d+dz][h+dy][w+dx] (padded coords), dz=k/9 etc.
// Each S element is read exactly once; MLP=27 streaming loads.
// ---------------------------------------------------------------------------
__global__ void __launch_bounds__(256)
sum_kernel()
{
    int idx = blockIdx.x * 256 + threadIdx.x;      // DD*HH*WW = 983040
    int w = idx % WW;
    int t = idx / WW;
    int h = t % HH;
    int d = t / HH;

    const float* base = g_S + (size_t)d*SLICE + h*ROWS + w;
    float acc = 0.0f;
#pragma unroll
    for (int k = 0; k < 27; ++k) {
        int dz = k / 9, dy = (k / 3) % 3, dx = k % 3;
        acc += __ldg(base + (size_t)k*CSTS + dz*SLICE + dy*ROWS + dx);
    }
    g_cost[d*HW + h*WW + w] = acc;
}

// ---------------------------------------------------------------------------
// Stage 4: softmax over D, expected depth + max-prob confidence.
// b_reg shifts all logits equally -> cancels in softmax -> ignored.
// ---------------------------------------------------------------------------
__global__ void __launch_bounds__(128)
depth_kernel(const float* __restrict__ depth_values, float* __restrict__ out)
{
    int pix = blockIdx.x * 128 + threadIdx.x;
    if (pix >= HW) return;

    float cv[DD];
    float m = -1e30f;
#pragma unroll
    for (int d = 0; d < DD; ++d) {
        cv[d] = g_cost[d*HW + pix];
        m = fmaxf(m, cv[d]);
    }
    float sum = 0.0f, dep = 0.0f, best = 0.0f;
#pragma unroll
    for (int d = 0; d < DD; ++d) {
        float e = expf(cv[d] - m);
        sum += e;
        dep += e * __ldg(depth_values + d);
        best = fmaxf(best, e);
    }
    float isum = 1.0f / sum;
    out[pix]      = dep * isum;
    out[HW + pix] = best * isum;
}

// ---------------------------------------------------------------------------
extern "C" void kernel_launch(void* const* d_in, const int* in_sizes, int n_in,
                              void* d_out, int out_size)
{
    const float* feat0 = (const float*)d_in[0];
    const float* feat1 = (const float*)d_in[1];
    const float* feat2 = (const float*)d_in[2];
    const float* proj  = (const float*)d_in[3];
    const float* dvals = (const float*)d_in[4];
    const float* wreg  = (const float*)d_in[5];
    float* out = (float*)d_out;

    prep_kernel<<<1, 1>>>(proj);
    transpose_kernel<<<dim3(HW/32, 3), dim3(32, 8)>>>(feat0, feat1, feat2);
    warp_var_kernel<<<DD*HH, 256>>>(dvals, wreg);
    sum_kernel<<<(DD*HH*WW)/256, 256>>>();
    depth_kernel<<<(HW + 127)/128, 128>>>(dvals, out);
}